// round 1
// baseline (speedup 1.0000x reference)
#include <cuda_runtime.h>
#include <math.h>

// ---------------------------------------------------------------------------
// SelfAttention: bs=4, n=2048, D=1024, H=8, dh=128
// out  = (softmax(QK^T + AP, masked))^T-applied attention -> proj
// aux  = A[:, last_head]   (full normalized attention of head 7)
// d_out layout: [ out (4*2048*1024) | A_last (4*2048*2048) ]  (tuple order)
// All math fp32 (FFMA); AP precomputed in double. Round-0 correctness-first,
// tiled-SGEMM-everywhere implementation.
// ---------------------------------------------------------------------------

namespace {
constexpr int BSZ  = 4;
constexpr int NSEQ = 2048;
constexpr int DM   = 1024;
constexpr int NH   = 8;
constexpr int DH   = 128;
constexpr float NEG_INF_F = -1e9f;
constexpr size_t OUT_A_OFF = (size_t)BSZ * NSEQ * DM;   // 8388608 floats
}

// Scratch (static device globals -- no allocations allowed)
__device__ float g_AP[(size_t)NSEQ * NSEQ];                    // 16 MB
__device__ float g_Q [(size_t)BSZ * NH * NSEQ * DH];           // 32 MB
__device__ float g_K [(size_t)BSZ * NH * NSEQ * DH];           // 32 MB
__device__ float g_V [(size_t)BSZ * NH * NSEQ * DH];           // 32 MB
__device__ float g_S [(size_t)BSZ * NH * NSEQ * NSEQ];         // 536 MB (scores -> P-hat in place)
__device__ float g_Y [(size_t)BSZ * NSEQ * DM];                // 32 MB
__device__ float g_rowM[BSZ * NH * NSEQ];
__device__ float g_rowZ[BSZ * NH * NSEQ];

// ---------------------------------------------------------------------------
// AP[p, 2i] = sin(p / 10000^(2i/1024));  AP[p, 2i+1] = cos(...)
// Computed once per launch in double (more accurate than the f32 reference;
// its own f32 quantization (~1e-4 abs) dominates the diff and is in budget).
// ---------------------------------------------------------------------------
__global__ void ap_kernel() {
    int idx = blockIdx.x * 256 + threadIdx.x;       // 0 .. 4M-1
    int p = idx >> 11;
    int c = idx & (NSEQ - 1);
    int i = c >> 1;
    double w   = exp(-((double)(2 * i) / (double)DM) * log(10000.0));
    double ang = (double)p * w;
    g_AP[idx] = (float)((c & 1) ? cos(ang) : sin(ang));
}

// ---------------------------------------------------------------------------
// Generic NT SGEMM: C[m,n] = sum_k A[m,k] * B[n,k]; both operands K-contiguous.
// 128x128 tile, BK=16, 256 threads, 8x8 microtile.
// EPI 0/1/2: QKV projection  (A=x [8192,1024], B=Wq/Wk/Wv [1024,1024])
//            -> scatter into g_Q/g_K/g_V as [b,h,n,e]
// EPI 3    : scores per (b,h)=blockIdx.z (A=Q slice, B=K slice, K=128)
//            -> S = QK^T + AP, masked -> g_S
// EPI 4    : output projection (A=g_Y [8192,1024], B=Wout [1024,1024]) -> d_out
// ---------------------------------------------------------------------------
template <int EPI>
__global__ __launch_bounds__(256) void gemm_nt(const float* __restrict__ Aext,
                                               const float* __restrict__ Bext,
                                               float* __restrict__ Cext,
                                               const int* __restrict__ mask) {
    constexpr int K = (EPI == 3) ? DH : DM;   // == lda == ldb in every use

    __shared__ float As[16][132];
    __shared__ float Bs[16][132];

    const int t  = threadIdx.x;
    const int bm = blockIdx.y * 128;
    const int bn = blockIdx.x * 128;

    const float* A;
    const float* B;
    if (EPI <= 2)      { A = Aext; B = Bext; }
    else if (EPI == 3) {
        size_t off = (size_t)blockIdx.z * NSEQ * DH;
        A = g_Q + off; B = g_K + off;
    } else             { A = g_Y; B = Bext; }

    const int lr = t >> 4;   // 0..15
    const int lk = t & 15;   // 0..15
    const int rm = lr * 8;
    const int rn = lk * 8;

    float acc[8][8];
#pragma unroll
    for (int i = 0; i < 8; i++)
#pragma unroll
        for (int j = 0; j < 8; j++) acc[i][j] = 0.f;

    for (int k0 = 0; k0 < K; k0 += 16) {
#pragma unroll
        for (int r = 0; r < 8; r++) {
            As[lk][lr + 16 * r] = A[(size_t)(bm + lr + 16 * r) * K + k0 + lk];
            Bs[lk][lr + 16 * r] = B[(size_t)(bn + lr + 16 * r) * K + k0 + lk];
        }
        __syncthreads();
#pragma unroll
        for (int kk = 0; kk < 16; kk++) {
            float a[8], b[8];
            *(float4*)(a)     = *(const float4*)&As[kk][rm];
            *(float4*)(a + 4) = *(const float4*)&As[kk][rm + 4];
            *(float4*)(b)     = *(const float4*)&Bs[kk][rn];
            *(float4*)(b + 4) = *(const float4*)&Bs[kk][rn + 4];
#pragma unroll
            for (int i = 0; i < 8; i++)
#pragma unroll
                for (int j = 0; j < 8; j++)
                    acc[i][j] = fmaf(a[i], b[j], acc[i][j]);
        }
        __syncthreads();
    }

#pragma unroll
    for (int i = 0; i < 8; i++) {
        const int row = bm + rm + i;
#pragma unroll
        for (int j = 0; j < 8; j++) {
            const int col = bn + rn + j;
            float v = acc[i][j];
            if (EPI <= 2) {
                float* Cb = (EPI == 0) ? g_Q : (EPI == 1) ? g_K : g_V;
                int b = row >> 11, n = row & (NSEQ - 1);
                int h = col >> 7,  e = col & (DH - 1);
                Cb[(((size_t)b * NH + h) * NSEQ + n) * DH + e] = v;
            } else if (EPI == 3) {
                int bh = blockIdx.z;
                int b  = bh >> 3;
                bool ok = (mask[b * NSEQ + row] != 0) && (mask[b * NSEQ + col] != 0);
                float s = ok ? (v + g_AP[(size_t)row * NSEQ + col]) : NEG_INF_F;
                g_S[(size_t)bh * NSEQ * NSEQ + (size_t)row * NSEQ + col] = s;
            } else {
                Cext[(size_t)row * DM + col] = v;
            }
        }
    }
}

// ---------------------------------------------------------------------------
// Per-row softmax stats: M[row]=max, Z[row]=1/sum(exp(S-M)). One block / row.
// Fully-masked rows: all entries == -1e9 -> M=-1e9, P=1, Z=1/2048 (== jax).
// ---------------------------------------------------------------------------
__global__ void rowstats_kernel() {
    __shared__ float red[256];
    const int row = blockIdx.x;                 // bh*2048 + j
    const float* S = g_S + (size_t)row * NSEQ;
    const int t = threadIdx.x;

    float m = -INFINITY;
    for (int c = t; c < NSEQ; c += 256) m = fmaxf(m, S[c]);
    red[t] = m; __syncthreads();
    for (int s = 128; s > 0; s >>= 1) {
        if (t < s) red[t] = fmaxf(red[t], red[t + s]);
        __syncthreads();
    }
    m = red[0];
    __syncthreads();

    float z = 0.f;
    for (int c = t; c < NSEQ; c += 256) z += expf(S[c] - m);
    red[t] = z; __syncthreads();
    for (int s = 128; s > 0; s >>= 1) {
        if (t < s) red[t] += red[t + s];
        __syncthreads();
    }
    if (t == 0) { g_rowM[row] = m; g_rowZ[row] = 1.f / red[0]; }
}

// ---------------------------------------------------------------------------
// P-hat = exp(S - M[row]) / Z[row], in place. For head 7 also stream the
// normalized rows straight into d_out's A_last region.
// ---------------------------------------------------------------------------
__global__ void normalize_kernel(float* __restrict__ Aout) {
    size_t i4 = ((size_t)blockIdx.x * 256 + threadIdx.x) * 4;
    int row = (int)(i4 >> 11);
    float m  = g_rowM[row];
    float zi = g_rowZ[row];
    float4 s = *reinterpret_cast<float4*>(&g_S[i4]);
    float4 p;
    p.x = expf(s.x - m) * zi;
    p.y = expf(s.y - m) * zi;
    p.z = expf(s.z - m) * zi;
    p.w = expf(s.w - m) * zi;
    *reinterpret_cast<float4*>(&g_S[i4]) = p;
    int bh = row >> 11;
    if ((bh & 7) == 7) {                         // head 7 -> A output
        int b = bh >> 3;
        size_t j   = (size_t)(row & (NSEQ - 1));
        size_t col = i4 & (NSEQ - 1);
        *reinterpret_cast<float4*>(
            &Aout[OUT_A_OFF + ((size_t)b * NSEQ + j) * NSEQ + col]) = p;
    }
}

// ---------------------------------------------------------------------------
// y[i,e] = sum_j Phat[j,i] * V[j,e]  (A-operand transposed: loads are [k][m]).
// One N-tile (DH=128). Writes g_Y[b, i, h*128 + e].
// ---------------------------------------------------------------------------
__global__ __launch_bounds__(256) void ptv_kernel() {
    __shared__ float As[16][132];
    __shared__ float Bs[16][132];
    const int t  = threadIdx.x;
    const int bh = blockIdx.z;
    const int bm = blockIdx.x * 128;
    const float* P = g_S + (size_t)bh * NSEQ * NSEQ;
    const float* V = g_V + (size_t)bh * NSEQ * DH;

    const int lr = t >> 4, lk = t & 15;
    const int rm = lr * 8, rn = lk * 8;
    const int lm  = t & 127;   // load column
    const int lkk = t >> 7;    // 0..1

    float acc[8][8];
#pragma unroll
    for (int i = 0; i < 8; i++)
#pragma unroll
        for (int j = 0; j < 8; j++) acc[i][j] = 0.f;

    for (int k0 = 0; k0 < NSEQ; k0 += 16) {
#pragma unroll
        for (int r = 0; r < 8; r++) {
            int k = lkk + 2 * r;
            As[k][lm] = P[(size_t)(k0 + k) * NSEQ + bm + lm];
            Bs[k][lm] = V[(size_t)(k0 + k) * DH + lm];
        }
        __syncthreads();
#pragma unroll
        for (int kk = 0; kk < 16; kk++) {
            float a[8], b[8];
            *(float4*)(a)     = *(const float4*)&As[kk][rm];
            *(float4*)(a + 4) = *(const float4*)&As[kk][rm + 4];
            *(float4*)(b)     = *(const float4*)&Bs[kk][rn];
            *(float4*)(b + 4) = *(const float4*)&Bs[kk][rn + 4];
#pragma unroll
            for (int i = 0; i < 8; i++)
#pragma unroll
                for (int j = 0; j < 8; j++)
                    acc[i][j] = fmaf(a[i], b[j], acc[i][j]);
        }
        __syncthreads();
    }

    const int b = bh >> 3, h = bh & 7;
#pragma unroll
    for (int i = 0; i < 8; i++) {
        const int ii = bm + rm + i;
#pragma unroll
        for (int j = 0; j < 8; j++) {
            const int e = rn + j;
            g_Y[((size_t)b * NSEQ + ii) * DM + h * DH + e] = acc[i][j];
        }
    }
}

// ---------------------------------------------------------------------------
extern "C" void kernel_launch(void* const* d_in, const int* in_sizes, int n_in,
                              void* d_out, int out_size) {
    const float* x    = (const float*)d_in[0];
    const int*   mask = (const int*)  d_in[1];
    const float* Wq   = (const float*)d_in[2];
    const float* Wk   = (const float*)d_in[3];
    const float* Wv   = (const float*)d_in[4];
    const float* Wout = (const float*)d_in[5];
    float* out = (float*)d_out;

    // 1) absolute-position table (independent of everything else)
    ap_kernel<<<(NSEQ * NSEQ) / 256, 256>>>();

    // 2) QKV projections: [8192,1024] x [1024,1024]^T, scattered to [b,h,n,e]
    dim3 gproj(DM / 128, (BSZ * NSEQ) / 128);          // (8, 64)
    gemm_nt<0><<<gproj, 256>>>(x, Wq, nullptr, nullptr);
    gemm_nt<1><<<gproj, 256>>>(x, Wk, nullptr, nullptr);
    gemm_nt<2><<<gproj, 256>>>(x, Wv, nullptr, nullptr);

    // 3) scores S = QK^T + AP, masked; per (b,h)
    gemm_nt<3><<<dim3(NSEQ / 128, NSEQ / 128, BSZ * NH), 256>>>(
        nullptr, nullptr, nullptr, mask);

    // 4) row softmax stats, then normalize in place (+ stream head-7 A to out)
    rowstats_kernel<<<BSZ * NH * NSEQ, 256>>>();
    normalize_kernel<<<(BSZ * NH * NSEQ) * (NSEQ / (4 * 256)), 256>>>(out);

    // 5) y = Phat^T V  (transposed attention apply)
    ptv_kernel<<<dim3(NSEQ / 128, 1, BSZ * NH), 256>>>();

    // 6) out = y @ Wout^T
    gemm_nt<4><<<gproj, 256>>>(nullptr, Wout, out, nullptr);
}

// round 6
// speedup vs baseline: 1.9071x; 1.9071x over previous
#include <cuda_runtime.h>
#include <cuda_bf16.h>
#include <math.h>

// ---------------------------------------------------------------------------
// SelfAttention: bs=4, n=2048, D=1024, H=8, dh=128
// All GEMMs on tensor cores (mma.sync m16n8k16 bf16) with 2-term bf16
// splitting (hi+lo) and f32 accumulation -> fp32-grade accuracy.
// d_out layout: [ out (4*2048*1024) | A_last (4*2048*2048) ]
// (Round 6 = resubmit: rounds 2-5 all died to broker/container infra;
//  this design has never executed on hardware.)
// ---------------------------------------------------------------------------

namespace {
constexpr int BSZ  = 4;
constexpr int NSEQ = 2048;
constexpr int DM   = 1024;
constexpr int NH   = 8;
constexpr int DH   = 128;
constexpr float NEG_INF_F = -1e9f;
constexpr size_t OUT_A_OFF = (size_t)BSZ * NSEQ * DM;
constexpr int LDK = 40;   // smem row stride in bf16 elems (32 + 8 pad)
}

// Scratch (static device globals -- no allocations allowed)
__device__ float g_AP[(size_t)NSEQ * NSEQ];                    // 16 MB
__device__ float g_Q [(size_t)BSZ * NH * NSEQ * DH];           // 32 MB
__device__ float g_K [(size_t)BSZ * NH * NSEQ * DH];           // 32 MB
__device__ float g_Vt[(size_t)BSZ * NH * DH * NSEQ];           // 32 MB (V transposed: [b,h,e,n])
__device__ float g_S [(size_t)BSZ * NH * NSEQ * NSEQ];         // 536 MB (S -> Phat in place)
__device__ float g_Y [(size_t)BSZ * NSEQ * DM];                // 32 MB

// ---------------------------------------------------------------------------
__global__ void ap_kernel() {
    int idx = blockIdx.x * 256 + threadIdx.x;
    int p = idx >> 11;
    int c = idx & (NSEQ - 1);
    int i = c >> 1;
    double w   = exp(-((double)(2 * i) / (double)DM) * log(10000.0));
    double ang = (double)p * w;
    g_AP[idx] = (float)((c & 1) ? cos(ang) : sin(ang));
}

// ---------------------------------------------------------------------------
__device__ __forceinline__ void mma16816(float* c, const unsigned* a, const unsigned* b) {
    asm volatile(
        "mma.sync.aligned.m16n8k16.row.col.f32.bf16.bf16.f32 "
        "{%0,%1,%2,%3},{%4,%5,%6,%7},{%8,%9},{%0,%1,%2,%3};"
        : "+f"(c[0]), "+f"(c[1]), "+f"(c[2]), "+f"(c[3])
        : "r"(a[0]), "r"(a[1]), "r"(a[2]), "r"(a[3]), "r"(b[0]), "r"(b[1]));
}

__device__ __forceinline__ void split_store(float v, __nv_bfloat16* hi, __nv_bfloat16* lo) {
    __nv_bfloat16 h = __float2bfloat16_rn(v);
    *hi = h;
    *lo = __float2bfloat16_rn(v - __bfloat162float(h));
}

// ---------------------------------------------------------------------------
// Tensor-core NT GEMM, 128x128x32 tiles, 8 warps (64x32 warp tiles).
// C[m,n] = sum_k A[m,k]*B[n,k], computed as hi*hi + hi*lo + lo*hi in bf16.
// EPI 0/1: QKV proj -> g_Q / g_K  ([b,h,n,e])
// EPI 2  : V proj   -> g_Vt      ([b,h,e,n])
// EPI 3  : scores per bh (K=128) -> S = QK^T + AP, masked
// EPI 4  : y = Phat^T V per bh (A transposed-staged, K=2048) -> g_Y
// EPI 5  : out proj -> d_out
// ---------------------------------------------------------------------------
template <int EPI>
__global__ __launch_bounds__(256) void tgemm(const float* __restrict__ Aext,
                                             const float* __restrict__ Bext,
                                             float* __restrict__ Cext,
                                             const int* __restrict__ mask) {
    constexpr int K   = (EPI == 3) ? 128 : (EPI == 4 ? 2048 : 1024);
    constexpr int LDA = K;
    constexpr int LDB = K;
    constexpr bool ATR = (EPI == 4);   // A stored [k][m] (P matrix)

    __shared__ __nv_bfloat16 As_hi[128 * LDK];
    __shared__ __nv_bfloat16 As_lo[128 * LDK];
    __shared__ __nv_bfloat16 Bs_hi[128 * LDK];
    __shared__ __nv_bfloat16 Bs_lo[128 * LDK];

    const int t    = threadIdx.x;
    const int lane = t & 31;
    const int warp = t >> 5;
    const int wm   = warp >> 2;        // 0..1
    const int wn   = warp & 3;         // 0..3
    const int grp  = lane >> 2;        // 0..7
    const int t4   = lane & 3;         // 0..3

    const int bm = blockIdx.y * 128;
    const int bn = blockIdx.x * 128;
    const int bh = (EPI == 3 || EPI == 4) ? blockIdx.z : 0;

    const float* A;
    const float* B;
    if (EPI <= 2)      { A = Aext; B = Bext; }
    else if (EPI == 3) {
        size_t off = (size_t)bh * NSEQ * DH;
        A = g_Q + off; B = g_K + off;
    } else if (EPI == 4) {
        A = g_S + (size_t)bh * NSEQ * NSEQ;
        B = g_Vt + (size_t)bh * DH * NSEQ;
    } else             { A = g_Y; B = Bext; }

    float acc[4][4][4];
#pragma unroll
    for (int i = 0; i < 4; i++)
#pragma unroll
        for (int j = 0; j < 4; j++)
#pragma unroll
            for (int q = 0; q < 4; q++) acc[i][j][q] = 0.f;

    for (int k0 = 0; k0 < K; k0 += 32) {
        // ---- stage A ----
        if (!ATR) {
#pragma unroll
            for (int r = 0; r < 4; r++) {
                int id = t + 256 * r;
                int m  = id >> 3;
                int c  = (id & 7) * 4;
                float4 v = *(const float4*)&A[(size_t)(bm + m) * LDA + k0 + c];
                split_store(v.x, &As_hi[m * LDK + c + 0], &As_lo[m * LDK + c + 0]);
                split_store(v.y, &As_hi[m * LDK + c + 1], &As_lo[m * LDK + c + 1]);
                split_store(v.z, &As_hi[m * LDK + c + 2], &As_lo[m * LDK + c + 2]);
                split_store(v.w, &As_hi[m * LDK + c + 3], &As_lo[m * LDK + c + 3]);
            }
        } else {
#pragma unroll
            for (int r = 0; r < 4; r++) {
                int id = t + 256 * r;
                int kk = id >> 5;
                int mc = (id & 31) * 4;
                float4 v = *(const float4*)&A[(size_t)(k0 + kk) * LDA + bm + mc];
                split_store(v.x, &As_hi[(mc + 0) * LDK + kk], &As_lo[(mc + 0) * LDK + kk]);
                split_store(v.y, &As_hi[(mc + 1) * LDK + kk], &As_lo[(mc + 1) * LDK + kk]);
                split_store(v.z, &As_hi[(mc + 2) * LDK + kk], &As_lo[(mc + 2) * LDK + kk]);
                split_store(v.w, &As_hi[(mc + 3) * LDK + kk], &As_lo[(mc + 3) * LDK + kk]);
            }
        }
        // ---- stage B ----
#pragma unroll
        for (int r = 0; r < 4; r++) {
            int id = t + 256 * r;
            int n  = id >> 3;
            int c  = (id & 7) * 4;
            float4 v = *(const float4*)&B[(size_t)(bn + n) * LDB + k0 + c];
            split_store(v.x, &Bs_hi[n * LDK + c + 0], &Bs_lo[n * LDK + c + 0]);
            split_store(v.y, &Bs_hi[n * LDK + c + 1], &Bs_lo[n * LDK + c + 1]);
            split_store(v.z, &Bs_hi[n * LDK + c + 2], &Bs_lo[n * LDK + c + 2]);
            split_store(v.w, &Bs_hi[n * LDK + c + 3], &Bs_lo[n * LDK + c + 3]);
        }
        __syncthreads();

#pragma unroll
        for (int ks = 0; ks < 32; ks += 16) {
            unsigned bhr[4][2], blr[4][2];
#pragma unroll
            for (int nt = 0; nt < 4; nt++) {
                int br = (wn * 32 + nt * 8 + grp) * LDK + ks + t4 * 2;
                bhr[nt][0] = *(const unsigned*)&Bs_hi[br];
                bhr[nt][1] = *(const unsigned*)&Bs_hi[br + 8];
                blr[nt][0] = *(const unsigned*)&Bs_lo[br];
                blr[nt][1] = *(const unsigned*)&Bs_lo[br + 8];
            }
#pragma unroll
            for (int mt = 0; mt < 4; mt++) {
                int ar = (wm * 64 + mt * 16 + grp) * LDK + ks + t4 * 2;
                unsigned ah[4], al[4];
                ah[0] = *(const unsigned*)&As_hi[ar];
                ah[1] = *(const unsigned*)&As_hi[ar + 8 * LDK];
                ah[2] = *(const unsigned*)&As_hi[ar + 8];
                ah[3] = *(const unsigned*)&As_hi[ar + 8 * LDK + 8];
                al[0] = *(const unsigned*)&As_lo[ar];
                al[1] = *(const unsigned*)&As_lo[ar + 8 * LDK];
                al[2] = *(const unsigned*)&As_lo[ar + 8];
                al[3] = *(const unsigned*)&As_lo[ar + 8 * LDK + 8];
#pragma unroll
                for (int nt = 0; nt < 4; nt++) {
                    mma16816(acc[mt][nt], ah, bhr[nt]);
                    mma16816(acc[mt][nt], ah, blr[nt]);
                    mma16816(acc[mt][nt], al, bhr[nt]);
                }
            }
        }
        __syncthreads();
    }

    // ---- epilogue ----
#pragma unroll
    for (int mt = 0; mt < 4; mt++) {
#pragma unroll
        for (int nt = 0; nt < 4; nt++) {
#pragma unroll
            for (int q = 0; q < 4; q++) {
                int row = bm + wm * 64 + mt * 16 + grp + ((q >> 1) ? 8 : 0);
                int col = bn + wn * 32 + nt * 8 + t4 * 2 + (q & 1);
                float v = acc[mt][nt][q];
                if (EPI <= 1) {
                    float* Cb = (EPI == 0) ? g_Q : g_K;
                    int b = row >> 11, n = row & (NSEQ - 1);
                    int h = col >> 7,  e = col & (DH - 1);
                    Cb[(((size_t)b * NH + h) * NSEQ + n) * DH + e] = v;
                } else if (EPI == 2) {
                    int b = row >> 11, n = row & (NSEQ - 1);
                    int h = col >> 7,  e = col & (DH - 1);
                    g_Vt[(((size_t)b * NH + h) * DH + e) * NSEQ + n] = v;
                } else if (EPI == 3) {
                    int b = bh >> 3;
                    bool ok = (mask[b * NSEQ + row] != 0) && (mask[b * NSEQ + col] != 0);
                    float s = ok ? (v + g_AP[(size_t)row * NSEQ + col]) : NEG_INF_F;
                    g_S[(size_t)bh * NSEQ * NSEQ + (size_t)row * NSEQ + col] = s;
                } else if (EPI == 4) {
                    int b = bh >> 3, h = bh & 7;
                    g_Y[((size_t)b * NSEQ + row) * DM + h * DH + col] = v;
                } else {
                    Cext[(size_t)row * DM + col] = v;
                }
            }
        }
    }
}

// ---------------------------------------------------------------------------
// Fused softmax: one block per row. max -> exp -> sum -> normalize in place.
// Head-7 rows also stream to d_out's A region.
// ---------------------------------------------------------------------------
__global__ __launch_bounds__(256) void softmax_kernel(float* __restrict__ Aout) {
    __shared__ float red[8];
    __shared__ float bcast;
    const int row = blockIdx.x;
    float* S = g_S + (size_t)row * NSEQ;
    const int t = threadIdx.x, lane = t & 31, warp = t >> 5;

    float4 v0 = *(float4*)&S[t * 4];
    float4 v1 = *(float4*)&S[(t + 256) * 4];

    float m = fmaxf(fmaxf(fmaxf(v0.x, v0.y), fmaxf(v0.z, v0.w)),
                    fmaxf(fmaxf(v1.x, v1.y), fmaxf(v1.z, v1.w)));
#pragma unroll
    for (int o = 16; o; o >>= 1) m = fmaxf(m, __shfl_xor_sync(~0u, m, o));
    if (lane == 0) red[warp] = m;
    __syncthreads();
    if (t == 0) {
        float mm = red[0];
#pragma unroll
        for (int i = 1; i < 8; i++) mm = fmaxf(mm, red[i]);
        bcast = mm;
    }
    __syncthreads();
    m = bcast;

    float4 p0, p1;
    p0.x = expf(v0.x - m); p0.y = expf(v0.y - m);
    p0.z = expf(v0.z - m); p0.w = expf(v0.w - m);
    p1.x = expf(v1.x - m); p1.y = expf(v1.y - m);
    p1.z = expf(v1.z - m); p1.w = expf(v1.w - m);

    float z = p0.x + p0.y + p0.z + p0.w + p1.x + p1.y + p1.z + p1.w;
#pragma unroll
    for (int o = 16; o; o >>= 1) z += __shfl_xor_sync(~0u, z, o);
    if (lane == 0) red[warp] = z;
    __syncthreads();
    if (t == 0) {
        float zz = 0.f;
#pragma unroll
        for (int i = 0; i < 8; i++) zz += red[i];
        bcast = 1.f / zz;
    }
    __syncthreads();
    float zi = bcast;

    p0.x *= zi; p0.y *= zi; p0.z *= zi; p0.w *= zi;
    p1.x *= zi; p1.y *= zi; p1.z *= zi; p1.w *= zi;
    *(float4*)&S[t * 4]         = p0;
    *(float4*)&S[(t + 256) * 4] = p1;

    const int bhh = row >> 11;
    if ((bhh & 7) == 7) {
        const int b = bhh >> 3;
        size_t base = OUT_A_OFF + ((size_t)b * NSEQ + (row & (NSEQ - 1))) * NSEQ;
        *(float4*)&Aout[base + t * 4]         = p0;
        *(float4*)&Aout[base + (t + 256) * 4] = p1;
    }
}

// ---------------------------------------------------------------------------
extern "C" void kernel_launch(void* const* d_in, const int* in_sizes, int n_in,
                              void* d_out, int out_size) {
    const float* x    = (const float*)d_in[0];
    const int*   mask = (const int*)  d_in[1];
    const float* Wq   = (const float*)d_in[2];
    const float* Wk   = (const float*)d_in[3];
    const float* Wv   = (const float*)d_in[4];
    const float* Wout = (const float*)d_in[5];
    float* out = (float*)d_out;

    ap_kernel<<<(NSEQ * NSEQ) / 256, 256>>>();

    dim3 gproj(DM / 128, (BSZ * NSEQ) / 128);          // (8, 64)
    tgemm<0><<<gproj, 256>>>(x, Wq, nullptr, nullptr);
    tgemm<1><<<gproj, 256>>>(x, Wk, nullptr, nullptr);
    tgemm<2><<<gproj, 256>>>(x, Wv, nullptr, nullptr);

    tgemm<3><<<dim3(NSEQ / 128, NSEQ / 128, BSZ * NH), 256>>>(
        nullptr, nullptr, nullptr, mask);

    softmax_kernel<<<BSZ * NH * NSEQ, 256>>>(out);

    tgemm<4><<<dim3(1, NSEQ / 128, BSZ * NH), 256>>>(nullptr, nullptr, nullptr, nullptr);

    tgemm<5><<<gproj, 256>>>(nullptr, Wout, out, nullptr);
}

// round 12
// speedup vs baseline: 2.7562x; 1.4452x over previous
#include <cuda_runtime.h>
#include <cuda_bf16.h>
#include <math.h>

// ---------------------------------------------------------------------------
// SelfAttention: bs=4, n=2048, D=1024, H=8, dh=128
// Round 12 (= round 10/11 resubmit; broker infra timeouts, kernel unmeasured):
// round-9 design with the AP launch-grid bug fixed (ap_kernel needs
// NSEQ*NSEQ/2 threads; round 9 launched NSEQ*DM/2 -> rel_err 0.23).
//   (a) AP table without fp64 transcendentals in the hot path
//   (b) double-buffered, register-prefetched tensor-core GEMMs
// All GEMMs: mma.sync m16n8k16 bf16, 2-term hi/lo split, f32 accumulate.
// d_out layout: [ out (4*2048*1024) | A_last (4*2048*2048) ]
// ---------------------------------------------------------------------------

namespace {
constexpr int BSZ  = 4;
constexpr int NSEQ = 2048;
constexpr int DM   = 1024;
constexpr int NH   = 8;
constexpr int DH   = 128;
constexpr float NEG_INF_F = -1e9f;
constexpr size_t OUT_A_OFF = (size_t)BSZ * NSEQ * DM;
constexpr int LDK  = 40;                     // smem row stride (32 + 8 pad), bf16
constexpr int TILE = 128 * LDK;              // one matrix tile, elems
constexpr int SSTR = 4 * TILE;               // one stage = Ah,Al,Bh,Bl
constexpr int SMEM_BYTES = 2 * SSTR * 2;     // two stages, bf16 -> 81920 B
}

// Scratch (static device globals -- no allocations allowed)
__device__ float  g_AP[(size_t)NSEQ * NSEQ];                   // 16 MB
__device__ float2 g_Wf[DM];                                    // 1024 (hi,lo) freqs
__device__ float  g_Q [(size_t)BSZ * NH * NSEQ * DH];          // 32 MB
__device__ float  g_K [(size_t)BSZ * NH * NSEQ * DH];          // 32 MB
__device__ float  g_Vt[(size_t)BSZ * NH * DH * NSEQ];          // 32 MB ([b,h,e,n])
__device__ float  g_S [(size_t)BSZ * NH * NSEQ * NSEQ];        // 536 MB (S -> Phat)
__device__ float  g_Y [(size_t)BSZ * NSEQ * DM];               // 32 MB

// ---------------------------------------------------------------------------
// Frequencies in double, once: w_i = 10000^(-2i/1024), split into hi+lo floats.
// ---------------------------------------------------------------------------
__global__ void w_kernel() {
    int i = blockIdx.x * 256 + threadIdx.x;          // 0..1023
    double w = exp(-2.0 * (double)i / (double)DM * log(10000.0));
    float whi = (float)w;
    float wlo = (float)(w - (double)whi);
    g_Wf[i] = make_float2(whi, wlo);
}

// ---------------------------------------------------------------------------
// AP[p,2i] = sin(p*w_i), AP[p,2i+1] = cos(p*w_i). All-fp32:
// TwoProd(p, whi) + p*wlo, then 3-term Cody-Waite mod-2pi, then sincosf.
// One thread per (sin,cos) pair: NSEQ rows x 1024 pairs = NSEQ*NSEQ/2 threads.
// ---------------------------------------------------------------------------
__global__ void ap_kernel() {
    int idx = blockIdx.x * 256 + threadIdx.x;        // 0 .. NSEQ*NSEQ/2 - 1
    int p = idx >> 10;                               // 0..2047
    int i = idx & 1023;                              // 0..1023
    float2 w = g_Wf[i];
    float fp = (float)p;
    float h = fp * w.x;
    float e = fmaf(fp, w.x, -h);                     // exact TwoProd error
    float t = fmaf(fp, w.y, e);                      // small correction

    constexpr double PI2D = 6.2831853071795864769252867665590058;
    constexpr float CW_A = 6.28125f;                              // 8-bit exact
    constexpr float CW_B = (float)(PI2D - (double)CW_A);
    constexpr float CW_C = (float)(PI2D - (double)CW_A - (double)CW_B);
    const float INV2PI = 0.15915494309189535f;

    float fn = rintf(h * INV2PI);                    // |fn| <= ~326 -> fn*CW_A exact
    float r = fmaf(-fn, CW_A, h);
    r = fmaf(-fn, CW_B, r);
    r = fmaf(-fn, CW_C, r);
    r += t;

    float s, c;
    sincosf(r, &s, &c);
    *(float2*)&g_AP[((size_t)p << 11) + 2 * i] = make_float2(s, c);
}

// ---------------------------------------------------------------------------
__device__ __forceinline__ void mma16816(float* c, const unsigned* a, const unsigned* b) {
    asm volatile(
        "mma.sync.aligned.m16n8k16.row.col.f32.bf16.bf16.f32 "
        "{%0,%1,%2,%3},{%4,%5,%6,%7},{%8,%9},{%0,%1,%2,%3};"
        : "+f"(c[0]), "+f"(c[1]), "+f"(c[2]), "+f"(c[3])
        : "r"(a[0]), "r"(a[1]), "r"(a[2]), "r"(a[3]), "r"(b[0]), "r"(b[1]));
}

// split float4 -> packed bf16x2 hi pair + lo pair (for one STS.64 each)
__device__ __forceinline__ void split_pack(float4 v, uint2& hi, uint2& lo) {
    __nv_bfloat162 h0 = __floats2bfloat162_rn(v.x, v.y);
    __nv_bfloat162 h1 = __floats2bfloat162_rn(v.z, v.w);
    float2 f0 = __bfloat1622float2(h0);
    float2 f1 = __bfloat1622float2(h1);
    __nv_bfloat162 l0 = __floats2bfloat162_rn(v.x - f0.x, v.y - f0.y);
    __nv_bfloat162 l1 = __floats2bfloat162_rn(v.z - f1.x, v.w - f1.y);
    hi = make_uint2(*(unsigned*)&h0, *(unsigned*)&h1);
    lo = make_uint2(*(unsigned*)&l0, *(unsigned*)&l1);
}

__device__ __forceinline__ void split1(float v, __nv_bfloat16* hi, __nv_bfloat16* lo) {
    __nv_bfloat16 h = __float2bfloat16_rn(v);
    *hi = h;
    *lo = __float2bfloat16_rn(v - __bfloat162float(h));
}

// ---------------------------------------------------------------------------
// Double-buffered tensor-core NT GEMM, 128x128x32 tiles, 8 warps.
// EPI 0/1: QKV proj -> g_Q / g_K    EPI 2: V proj -> g_Vt (transposed)
// EPI 3: scores (+AP, mask) -> g_S  EPI 4: Phat^T V -> g_Y   EPI 5: out proj
// ---------------------------------------------------------------------------
template <int EPI>
__global__ __launch_bounds__(256) void tgemm(const float* __restrict__ Aext,
                                             const float* __restrict__ Bext,
                                             float* __restrict__ Cext,
                                             const int* __restrict__ mask) {
    constexpr int K    = (EPI == 3) ? 128 : (EPI == 4 ? 2048 : 1024);
    constexpr int LDA  = K;
    constexpr int LDB  = K;
    constexpr bool ATR = (EPI == 4);             // A stored [k][m] (P matrix)
    constexpr int NBLK = K / 32;

    extern __shared__ __nv_bfloat16 sm[];

    const int t    = threadIdx.x;
    const int lane = t & 31;
    const int warp = t >> 5;
    const int wm   = warp >> 2;
    const int wn   = warp & 3;
    const int grp  = lane >> 2;
    const int t4   = lane & 3;

    const int bm = blockIdx.y * 128;
    const int bn = blockIdx.x * 128;
    const int bh = (EPI == 3 || EPI == 4) ? blockIdx.z : 0;

    const float* A;
    const float* B;
    if (EPI <= 2)      { A = Aext; B = Bext; }
    else if (EPI == 3) {
        size_t off = (size_t)bh * NSEQ * DH;
        A = g_Q + off; B = g_K + off;
    } else if (EPI == 4) {
        A = g_S + (size_t)bh * NSEQ * NSEQ;
        B = g_Vt + (size_t)bh * DH * NSEQ;
    } else             { A = g_Y; B = Bext; }

    float4 ra[4], rb[4];

    auto load_g = [&](int k0) {
#pragma unroll
        for (int r = 0; r < 4; r++) {
            int id = t + 256 * r;
            if (!ATR) {
                int m = id >> 3, c = (id & 7) * 4;
                ra[r] = *(const float4*)&A[(size_t)(bm + m) * LDA + k0 + c];
            } else {
                int kk = id >> 5, mc = (id & 31) * 4;
                ra[r] = *(const float4*)&A[(size_t)(k0 + kk) * LDA + bm + mc];
            }
            int n = id >> 3, c = (id & 7) * 4;
            rb[r] = *(const float4*)&B[(size_t)(bn + n) * LDB + k0 + c];
        }
    };

    auto store_s = [&](int stg) {
        __nv_bfloat16* Ah = sm + stg * SSTR;
        __nv_bfloat16* Al = Ah + TILE;
        __nv_bfloat16* Bh = Al + TILE;
        __nv_bfloat16* Bl = Bh + TILE;
#pragma unroll
        for (int r = 0; r < 4; r++) {
            int id = t + 256 * r;
            if (!ATR) {
                int m = id >> 3, c = (id & 7) * 4;
                uint2 hi, lo;
                split_pack(ra[r], hi, lo);
                *(uint2*)&Ah[m * LDK + c] = hi;
                *(uint2*)&Al[m * LDK + c] = lo;
            } else {
                int kk = id >> 5, mc = (id & 31) * 4;
                split1(ra[r].x, &Ah[(mc + 0) * LDK + kk], &Al[(mc + 0) * LDK + kk]);
                split1(ra[r].y, &Ah[(mc + 1) * LDK + kk], &Al[(mc + 1) * LDK + kk]);
                split1(ra[r].z, &Ah[(mc + 2) * LDK + kk], &Al[(mc + 2) * LDK + kk]);
                split1(ra[r].w, &Ah[(mc + 3) * LDK + kk], &Al[(mc + 3) * LDK + kk]);
            }
            int n = id >> 3, c = (id & 7) * 4;
            uint2 hi, lo;
            split_pack(rb[r], hi, lo);
            *(uint2*)&Bh[n * LDK + c] = hi;
            *(uint2*)&Bl[n * LDK + c] = lo;
        }
    };

    float acc[4][4][4];
#pragma unroll
    for (int i = 0; i < 4; i++)
#pragma unroll
        for (int j = 0; j < 4; j++)
#pragma unroll
            for (int q = 0; q < 4; q++) acc[i][j][q] = 0.f;

    // prologue: stage block 0
    load_g(0);
    store_s(0);
    __syncthreads();

    for (int blk = 0; blk < NBLK; blk++) {
        const int cur = blk & 1;
        if (blk + 1 < NBLK) load_g((blk + 1) * 32);   // prefetch (hidden by MMAs)

        const __nv_bfloat16* Ah = sm + cur * SSTR;
        const __nv_bfloat16* Al = Ah + TILE;
        const __nv_bfloat16* Bh = Al + TILE;
        const __nv_bfloat16* Bl = Bh + TILE;

#pragma unroll
        for (int ks = 0; ks < 32; ks += 16) {
            unsigned bhr[4][2], blr[4][2];
#pragma unroll
            for (int nt = 0; nt < 4; nt++) {
                int br = (wn * 32 + nt * 8 + grp) * LDK + ks + t4 * 2;
                bhr[nt][0] = *(const unsigned*)&Bh[br];
                bhr[nt][1] = *(const unsigned*)&Bh[br + 8];
                blr[nt][0] = *(const unsigned*)&Bl[br];
                blr[nt][1] = *(const unsigned*)&Bl[br + 8];
            }
#pragma unroll
            for (int mt = 0; mt < 4; mt++) {
                int ar = (wm * 64 + mt * 16 + grp) * LDK + ks + t4 * 2;
                unsigned ah[4], al[4];
                ah[0] = *(const unsigned*)&Ah[ar];
                ah[1] = *(const unsigned*)&Ah[ar + 8 * LDK];
                ah[2] = *(const unsigned*)&Ah[ar + 8];
                ah[3] = *(const unsigned*)&Ah[ar + 8 * LDK + 8];
                al[0] = *(const unsigned*)&Al[ar];
                al[1] = *(const unsigned*)&Al[ar + 8 * LDK];
                al[2] = *(const unsigned*)&Al[ar + 8];
                al[3] = *(const unsigned*)&Al[ar + 8 * LDK + 8];
#pragma unroll
                for (int nt = 0; nt < 4; nt++) {
                    mma16816(acc[mt][nt], ah, bhr[nt]);
                    mma16816(acc[mt][nt], ah, blr[nt]);
                    mma16816(acc[mt][nt], al, bhr[nt]);
                }
            }
        }

        if (blk + 1 < NBLK) store_s(cur ^ 1);
        __syncthreads();
    }

    // ---- epilogue ----
#pragma unroll
    for (int mt = 0; mt < 4; mt++) {
#pragma unroll
        for (int nt = 0; nt < 4; nt++) {
#pragma unroll
            for (int q = 0; q < 4; q++) {
                int row = bm + wm * 64 + mt * 16 + grp + ((q >> 1) ? 8 : 0);
                int col = bn + wn * 32 + nt * 8 + t4 * 2 + (q & 1);
                float v = acc[mt][nt][q];
                if (EPI <= 1) {
                    float* Cb = (EPI == 0) ? g_Q : g_K;
                    int b = row >> 11, n = row & (NSEQ - 1);
                    int h = col >> 7,  e = col & (DH - 1);
                    Cb[(((size_t)b * NH + h) * NSEQ + n) * DH + e] = v;
                } else if (EPI == 2) {
                    int b = row >> 11, n = row & (NSEQ - 1);
                    int h = col >> 7,  e = col & (DH - 1);
                    g_Vt[(((size_t)b * NH + h) * DH + e) * NSEQ + n] = v;
                } else if (EPI == 3) {
                    int b = bh >> 3;
                    bool ok = (mask[b * NSEQ + row] != 0) && (mask[b * NSEQ + col] != 0);
                    float s = ok ? (v + g_AP[(size_t)row * NSEQ + col]) : NEG_INF_F;
                    g_S[(size_t)bh * NSEQ * NSEQ + (size_t)row * NSEQ + col] = s;
                } else if (EPI == 4) {
                    int b = bh >> 3, h = bh & 7;
                    g_Y[((size_t)b * NSEQ + row) * DM + h * DH + col] = v;
                } else {
                    Cext[(size_t)row * DM + col] = v;
                }
            }
        }
    }
}

// ---------------------------------------------------------------------------
// Fused softmax: one block per row; head-7 rows also stream to d_out.
// ---------------------------------------------------------------------------
__global__ __launch_bounds__(256) void softmax_kernel(float* __restrict__ Aout) {
    __shared__ float red[8];
    __shared__ float bcast;
    const int row = blockIdx.x;
    float* S = g_S + (size_t)row * NSEQ;
    const int t = threadIdx.x, lane = t & 31, warp = t >> 5;

    float4 v0 = *(float4*)&S[t * 4];
    float4 v1 = *(float4*)&S[(t + 256) * 4];

    float m = fmaxf(fmaxf(fmaxf(v0.x, v0.y), fmaxf(v0.z, v0.w)),
                    fmaxf(fmaxf(v1.x, v1.y), fmaxf(v1.z, v1.w)));
#pragma unroll
    for (int o = 16; o; o >>= 1) m = fmaxf(m, __shfl_xor_sync(~0u, m, o));
    if (lane == 0) red[warp] = m;
    __syncthreads();
    if (t == 0) {
        float mm = red[0];
#pragma unroll
        for (int i = 1; i < 8; i++) mm = fmaxf(mm, red[i]);
        bcast = mm;
    }
    __syncthreads();
    m = bcast;

    float4 p0, p1;
    p0.x = expf(v0.x - m); p0.y = expf(v0.y - m);
    p0.z = expf(v0.z - m); p0.w = expf(v0.w - m);
    p1.x = expf(v1.x - m); p1.y = expf(v1.y - m);
    p1.z = expf(v1.z - m); p1.w = expf(v1.w - m);

    float z = p0.x + p0.y + p0.z + p0.w + p1.x + p1.y + p1.z + p1.w;
#pragma unroll
    for (int o = 16; o; o >>= 1) z += __shfl_xor_sync(~0u, z, o);
    if (lane == 0) red[warp] = z;
    __syncthreads();
    if (t == 0) {
        float zz = 0.f;
#pragma unroll
        for (int i = 0; i < 8; i++) zz += red[i];
        bcast = 1.f / zz;
    }
    __syncthreads();
    float zi = bcast;

    p0.x *= zi; p0.y *= zi; p0.z *= zi; p0.w *= zi;
    p1.x *= zi; p1.y *= zi; p1.z *= zi; p1.w *= zi;
    *(float4*)&S[t * 4]         = p0;
    *(float4*)&S[(t + 256) * 4] = p1;

    const int bhh = row >> 11;
    if ((bhh & 7) == 7) {
        const int b = bhh >> 3;
        size_t base = OUT_A_OFF + ((size_t)b * NSEQ + (row & (NSEQ - 1))) * NSEQ;
        *(float4*)&Aout[base + t * 4]         = p0;
        *(float4*)&Aout[base + (t + 256) * 4] = p1;
    }
}

// ---------------------------------------------------------------------------
extern "C" void kernel_launch(void* const* d_in, const int* in_sizes, int n_in,
                              void* d_out, int out_size) {
    const float* x    = (const float*)d_in[0];
    const int*   mask = (const int*)  d_in[1];
    const float* Wq   = (const float*)d_in[2];
    const float* Wk   = (const float*)d_in[3];
    const float* Wv   = (const float*)d_in[4];
    const float* Wout = (const float*)d_in[5];
    float* out = (float*)d_out;

    // Unconditional (idempotent, not a stream op, capture-safe) — no static
    // guard per the harness determinism rules.
    cudaFuncSetAttribute(tgemm<0>, cudaFuncAttributeMaxDynamicSharedMemorySize, SMEM_BYTES);
    cudaFuncSetAttribute(tgemm<1>, cudaFuncAttributeMaxDynamicSharedMemorySize, SMEM_BYTES);
    cudaFuncSetAttribute(tgemm<2>, cudaFuncAttributeMaxDynamicSharedMemorySize, SMEM_BYTES);
    cudaFuncSetAttribute(tgemm<3>, cudaFuncAttributeMaxDynamicSharedMemorySize, SMEM_BYTES);
    cudaFuncSetAttribute(tgemm<4>, cudaFuncAttributeMaxDynamicSharedMemorySize, SMEM_BYTES);
    cudaFuncSetAttribute(tgemm<5>, cudaFuncAttributeMaxDynamicSharedMemorySize, SMEM_BYTES);

    w_kernel<<<4, 256>>>();
    // NSEQ*NSEQ/2 threads (one per sin/cos pair) — full 2048-row coverage.
    ap_kernel<<<((size_t)NSEQ * NSEQ / 2) / 256, 256>>>();

    dim3 gproj(DM / 128, (BSZ * NSEQ) / 128);          // (8, 64)
    tgemm<0><<<gproj, 256, SMEM_BYTES>>>(x, Wq, nullptr, nullptr);
    tgemm<1><<<gproj, 256, SMEM_BYTES>>>(x, Wk, nullptr, nullptr);
    tgemm<2><<<gproj, 256, SMEM_BYTES>>>(x, Wv, nullptr, nullptr);

    tgemm<3><<<dim3(NSEQ / 128, NSEQ / 128, BSZ * NH), 256, SMEM_BYTES>>>(
        nullptr, nullptr, nullptr, mask);

    softmax_kernel<<<BSZ * NH * NSEQ, 256>>>(out);

    tgemm<4><<<dim3(1, NSEQ / 128, BSZ * NH), 256, SMEM_BYTES>>>(
        nullptr, nullptr, nullptr, nullptr);

    tgemm<5><<<gproj, 256, SMEM_BYTES>>>(nullptr, Wout, out, nullptr);
}

// round 13
// speedup vs baseline: 3.4182x; 1.2402x over previous
#include <cuda_runtime.h>
#include <cuda_bf16.h>
#include <math.h>

// ---------------------------------------------------------------------------
// SelfAttention: bs=4, n=2048, D=1024, H=8, dh=128
// Round 13: pre-split bf16 hi/lo operands in GMEM + pure cp.async staging.
//  - conversion math removed from all GEMM hot loops
//  - regs < 128 -> 2 CTAs/SM (occ 25%) via __launch_bounds__(256,2)
//  - S stays fp32 for softmax precision; everything else bf16 pairs
// All GEMMs: mma.sync m16n8k16 bf16, 3-MMA hi/lo split, f32 accumulate.
// d_out layout: [ out (4*2048*1024) | A_last (4*2048*2048) ]
// ---------------------------------------------------------------------------

namespace {
constexpr int BSZ  = 4;
constexpr int NSEQ = 2048;
constexpr int DM   = 1024;
constexpr int NH   = 8;
constexpr int DH   = 128;
constexpr float NEG_INF_F = -1e9f;
constexpr size_t OUT_A_OFF = (size_t)BSZ * NSEQ * DM;
constexpr int LDK  = 40;                     // smem row stride (32 + 8 pad), bf16
constexpr int TILE = 128 * LDK;              // one matrix tile, elems
constexpr int SSTR = 4 * TILE;               // one stage = Ah,Al,Bh,Bl
constexpr int SMEM_BYTES = 2 * SSTR * 2;     // two stages -> 81920 B
}

// ---- device-global scratch (no allocations allowed) ----
__device__ float  g_AP[(size_t)NSEQ * NSEQ];                      // 16 MB
__device__ float2 g_Wf[DM];
__device__ float  g_S [(size_t)BSZ * NH * NSEQ * NSEQ];           // 536 MB fp32
// bf16 hi/lo pairs
__device__ __nv_bfloat16 g_xh [(size_t)BSZ * NSEQ * DM], g_xl [(size_t)BSZ * NSEQ * DM];
__device__ __nv_bfloat16 g_Wqh[DM * DM], g_Wql[DM * DM];
__device__ __nv_bfloat16 g_Wkh[DM * DM], g_Wkl[DM * DM];
__device__ __nv_bfloat16 g_Wvh[DM * DM], g_Wvl[DM * DM];
__device__ __nv_bfloat16 g_Woh[DM * DM], g_Wol[DM * DM];
__device__ __nv_bfloat16 g_Qh [(size_t)BSZ * NH * NSEQ * DH], g_Ql [(size_t)BSZ * NH * NSEQ * DH];
__device__ __nv_bfloat16 g_Kh [(size_t)BSZ * NH * NSEQ * DH], g_Kl [(size_t)BSZ * NH * NSEQ * DH];
__device__ __nv_bfloat16 g_Vth[(size_t)BSZ * NH * DH * NSEQ], g_Vtl[(size_t)BSZ * NH * DH * NSEQ];
__device__ __nv_bfloat16 g_Ph [(size_t)BSZ * NH * NSEQ * NSEQ], g_Pl [(size_t)BSZ * NH * NSEQ * NSEQ];
__device__ __nv_bfloat16 g_Yh [(size_t)BSZ * NSEQ * DM], g_Yl [(size_t)BSZ * NSEQ * DM];

#define CP16(dst, src) \
    asm volatile("cp.async.cg.shared.global [%0], [%1], 16;" :: "r"(dst), "l"(src) : "memory")
#define CP_COMMIT() asm volatile("cp.async.commit_group;" ::: "memory")

// ---------------------------------------------------------------------------
__global__ void w_kernel() {
    int i = blockIdx.x * 256 + threadIdx.x;
    double w = exp(-2.0 * (double)i / (double)DM * log(10000.0));
    float whi = (float)w;
    g_Wf[i] = make_float2(whi, (float)(w - (double)whi));
}

__global__ void ap_kernel() {
    int idx = blockIdx.x * 256 + threadIdx.x;        // 0 .. NSEQ*NSEQ/2-1
    int p = idx >> 10;
    int i = idx & 1023;
    float2 w = g_Wf[i];
    float fp = (float)p;
    float h = fp * w.x;
    float e = fmaf(fp, w.x, -h);
    float t = fmaf(fp, w.y, e);

    constexpr double PI2D = 6.2831853071795864769252867665590058;
    constexpr float CW_A = 6.28125f;
    constexpr float CW_B = (float)(PI2D - (double)CW_A);
    constexpr float CW_C = (float)(PI2D - (double)CW_A - (double)CW_B);
    const float INV2PI = 0.15915494309189535f;

    float fn = rintf(h * INV2PI);
    float r = fmaf(-fn, CW_A, h);
    r = fmaf(-fn, CW_B, r);
    r = fmaf(-fn, CW_C, r);
    r += t;
    float s, c;
    sincosf(r, &s, &c);
    *(float2*)&g_AP[((size_t)p << 11) + 2 * i] = make_float2(s, c);
}

// fp32 -> (hi, lo) bf16 pair split, vectorized
__device__ __forceinline__ void split_pack(float4 v, uint2& hi, uint2& lo) {
    __nv_bfloat162 h0 = __floats2bfloat162_rn(v.x, v.y);
    __nv_bfloat162 h1 = __floats2bfloat162_rn(v.z, v.w);
    float2 f0 = __bfloat1622float2(h0);
    float2 f1 = __bfloat1622float2(h1);
    __nv_bfloat162 l0 = __floats2bfloat162_rn(v.x - f0.x, v.y - f0.y);
    __nv_bfloat162 l1 = __floats2bfloat162_rn(v.z - f1.x, v.w - f1.y);
    hi = make_uint2(*(unsigned*)&h0, *(unsigned*)&h1);
    lo = make_uint2(*(unsigned*)&l0, *(unsigned*)&l1);
}

__global__ __launch_bounds__(256) void conv_kernel(const float* __restrict__ src,
                                                   __nv_bfloat16* __restrict__ dh,
                                                   __nv_bfloat16* __restrict__ dl) {
    size_t i4 = ((size_t)blockIdx.x * 256 + threadIdx.x) * 4;
    float4 v = *(const float4*)&src[i4];
    uint2 hi, lo;
    split_pack(v, hi, lo);
    *(uint2*)&dh[i4] = hi;
    *(uint2*)&dl[i4] = lo;
}

// ---------------------------------------------------------------------------
__device__ __forceinline__ void mma16816(float* c, const unsigned* a, const unsigned* b) {
    asm volatile(
        "mma.sync.aligned.m16n8k16.row.col.f32.bf16.bf16.f32 "
        "{%0,%1,%2,%3},{%4,%5,%6,%7},{%8,%9},{%0,%1,%2,%3};"
        : "+f"(c[0]), "+f"(c[1]), "+f"(c[2]), "+f"(c[3])
        : "r"(a[0]), "r"(a[1]), "r"(a[2]), "r"(a[3]), "r"(b[0]), "r"(b[1]));
}

// ---------------------------------------------------------------------------
// Tensor-core NT GEMM over pre-split bf16 operands, 128x128x32 tiles, 8 warps,
// two cp.async stages. EPI 0/1: proj -> Q/K pairs. EPI 2: -> Vt pairs.
// EPI 3: scores (+AP, mask) -> S fp32. EPI 4: P^T V -> Y pairs (A transposed,
// register-prefetch staged). EPI 5: out proj -> d_out fp32.
// ---------------------------------------------------------------------------
template <int EPI>
__global__ __launch_bounds__(256, 2) void tgemm(float* __restrict__ Cext,
                                                const int* __restrict__ mask) {
    constexpr int K    = (EPI == 3) ? 128 : (EPI == 4 ? 2048 : 1024);
    constexpr bool ATR = (EPI == 4);
    constexpr int NBLK = K / 32;

    extern __shared__ __nv_bfloat16 sm[];
    const unsigned smem_u32 = (unsigned)__cvta_generic_to_shared(sm);

    const int t    = threadIdx.x;
    const int lane = t & 31;
    const int warp = t >> 5;
    const int wm   = warp >> 2;
    const int wn   = warp & 3;
    const int grp  = lane >> 2;
    const int t4   = lane & 3;

    const int bm = blockIdx.y * 128;
    const int bn = blockIdx.x * 128;
    const int bh = (EPI == 3 || EPI == 4) ? blockIdx.z : 0;

    const __nv_bfloat16 *Ah, *Al, *Bh, *Bl;
    if (EPI == 0)      { Ah = g_xh; Al = g_xl; Bh = g_Wqh; Bl = g_Wql; }
    else if (EPI == 1) { Ah = g_xh; Al = g_xl; Bh = g_Wkh; Bl = g_Wkl; }
    else if (EPI == 2) { Ah = g_xh; Al = g_xl; Bh = g_Wvh; Bl = g_Wvl; }
    else if (EPI == 3) {
        size_t off = (size_t)bh * NSEQ * DH;
        Ah = g_Qh + off; Al = g_Ql + off; Bh = g_Kh + off; Bl = g_Kl + off;
    } else if (EPI == 4) {
        size_t ao = (size_t)bh * NSEQ * NSEQ, bo = (size_t)bh * DH * NSEQ;
        Ah = g_Ph + ao; Al = g_Pl + ao; Bh = g_Vth + bo; Bl = g_Vtl + bo;
    } else             { Ah = g_Yh; Al = g_Yl; Bh = g_Woh; Bl = g_Wol; }

    // cp.async staging of one 128x32 bf16 tile set (skips A when ATR)
    auto stage_cp = [&](int k0, int stg) {
        unsigned smb = smem_u32 + (unsigned)(stg * SSTR * 2);
#pragma unroll
        for (int arr = (ATR ? 2 : 0); arr < 4; arr++) {
            const __nv_bfloat16* g = (arr == 0) ? Ah : (arr == 1) ? Al
                                   : (arr == 2) ? Bh : Bl;
            const int rc = (arr < 2) ? bm : bn;
#pragma unroll
            for (int r = 0; r < 2; r++) {
                int chunk = t + 256 * r;         // 0..511
                int row = chunk >> 2;            // 0..127
                int cb  = (chunk & 3) * 8;       // 0,8,16,24 (bf16)
                CP16(smb + (unsigned)((arr * TILE + row * LDK + cb) * 2),
                     g + (size_t)(rc + row) * K + k0 + cb);
            }
        }
    };

    // ATR (P^T) staging: loads issued early into regs, stores after MMAs
    uint2 avh[4], avl[4];
    auto atr_load = [&](int k0) {
#pragma unroll
        for (int r = 0; r < 4; r++) {
            int id = t + 256 * r;                // 0..1023
            int kk = id >> 5;                    // 0..31
            int mc = (id & 31) * 4;              // 0..124
            avh[r] = *(const uint2*)&Ah[(size_t)(k0 + kk) * K + bm + mc];
            avl[r] = *(const uint2*)&Al[(size_t)(k0 + kk) * K + bm + mc];
        }
    };
    auto atr_store = [&](int stg) {
        __nv_bfloat16* As_h = sm + stg * SSTR;
        __nv_bfloat16* As_l = As_h + TILE;
#pragma unroll
        for (int r = 0; r < 4; r++) {
            int id = t + 256 * r;
            int kk = id >> 5;
            int mc = (id & 31) * 4;
            __nv_bfloat162 h0 = *(__nv_bfloat162*)&avh[r].x;
            __nv_bfloat162 h1 = *(__nv_bfloat162*)&avh[r].y;
            __nv_bfloat162 l0 = *(__nv_bfloat162*)&avl[r].x;
            __nv_bfloat162 l1 = *(__nv_bfloat162*)&avl[r].y;
            As_h[(mc + 0) * LDK + kk] = __low2bfloat16(h0);
            As_h[(mc + 1) * LDK + kk] = __high2bfloat16(h0);
            As_h[(mc + 2) * LDK + kk] = __low2bfloat16(h1);
            As_h[(mc + 3) * LDK + kk] = __high2bfloat16(h1);
            As_l[(mc + 0) * LDK + kk] = __low2bfloat16(l0);
            As_l[(mc + 1) * LDK + kk] = __high2bfloat16(l0);
            As_l[(mc + 2) * LDK + kk] = __low2bfloat16(l1);
            As_l[(mc + 3) * LDK + kk] = __high2bfloat16(l1);
        }
    };

    float acc[4][4][4];
#pragma unroll
    for (int i = 0; i < 4; i++)
#pragma unroll
        for (int j = 0; j < 4; j++)
#pragma unroll
            for (int q = 0; q < 4; q++) acc[i][j][q] = 0.f;

    // prologue
    if (ATR) { atr_load(0); atr_store(0); }
    stage_cp(0, 0);
    CP_COMMIT();

    for (int blk = 0; blk < NBLK; blk++) {
        const int cur = blk & 1;
        if (blk + 1 < NBLK) {
            if (ATR) atr_load((blk + 1) * 32);
            stage_cp((blk + 1) * 32, cur ^ 1);
            CP_COMMIT();
            asm volatile("cp.async.wait_group 1;" ::: "memory");
        } else {
            asm volatile("cp.async.wait_group 0;" ::: "memory");
        }
        __syncthreads();

        const __nv_bfloat16* Ahs = sm + cur * SSTR;
        const __nv_bfloat16* Als = Ahs + TILE;
        const __nv_bfloat16* Bhs = Als + TILE;
        const __nv_bfloat16* Bls = Bhs + TILE;

#pragma unroll
        for (int ks = 0; ks < 32; ks += 16) {
            unsigned bhr[4][2], blr[4][2];
#pragma unroll
            for (int nt = 0; nt < 4; nt++) {
                int br = (wn * 32 + nt * 8 + grp) * LDK + ks + t4 * 2;
                bhr[nt][0] = *(const unsigned*)&Bhs[br];
                bhr[nt][1] = *(const unsigned*)&Bhs[br + 8];
                blr[nt][0] = *(const unsigned*)&Bls[br];
                blr[nt][1] = *(const unsigned*)&Bls[br + 8];
            }
#pragma unroll
            for (int mt = 0; mt < 4; mt++) {
                int ar = (wm * 64 + mt * 16 + grp) * LDK + ks + t4 * 2;
                unsigned ah[4], al[4];
                ah[0] = *(const unsigned*)&Ahs[ar];
                ah[1] = *(const unsigned*)&Ahs[ar + 8 * LDK];
                ah[2] = *(const unsigned*)&Ahs[ar + 8];
                ah[3] = *(const unsigned*)&Ahs[ar + 8 * LDK + 8];
                al[0] = *(const unsigned*)&Als[ar];
                al[1] = *(const unsigned*)&Als[ar + 8 * LDK];
                al[2] = *(const unsigned*)&Als[ar + 8];
                al[3] = *(const unsigned*)&Als[ar + 8 * LDK + 8];
#pragma unroll
                for (int nt = 0; nt < 4; nt++) {
                    mma16816(acc[mt][nt], ah, bhr[nt]);
                    mma16816(acc[mt][nt], ah, blr[nt]);
                    mma16816(acc[mt][nt], al, bhr[nt]);
                }
            }
        }

        if (ATR && blk + 1 < NBLK) atr_store(cur ^ 1);
        __syncthreads();
    }

    // ---- epilogue ----
#pragma unroll
    for (int mt = 0; mt < 4; mt++) {
#pragma unroll
        for (int nt = 0; nt < 4; nt++) {
#pragma unroll
            for (int half = 0; half < 2; half++) {
                const int row = bm + wm * 64 + mt * 16 + grp + half * 8;
                const int col = bn + wn * 32 + nt * 8 + t4 * 2;
                const float vx = acc[mt][nt][half * 2 + 0];
                const float vy = acc[mt][nt][half * 2 + 1];
                if (EPI <= 1) {
                    __nv_bfloat162 h = __floats2bfloat162_rn(vx, vy);
                    float2 f = __bfloat1622float2(h);
                    __nv_bfloat162 l = __floats2bfloat162_rn(vx - f.x, vy - f.y);
                    int b = row >> 11, n = row & (NSEQ - 1);
                    int hh = col >> 7, e = col & (DH - 1);
                    size_t o = (((size_t)b * NH + hh) * NSEQ + n) * DH + e;
                    if (EPI == 0) { *(__nv_bfloat162*)&g_Qh[o] = h; *(__nv_bfloat162*)&g_Ql[o] = l; }
                    else          { *(__nv_bfloat162*)&g_Kh[o] = h; *(__nv_bfloat162*)&g_Kl[o] = l; }
                } else if (EPI == 2) {
                    int b = row >> 11, n = row & (NSEQ - 1);
                    int hh = col >> 7, e = col & (DH - 1);
                    size_t o = (((size_t)b * NH + hh) * DH + e) * NSEQ + n;
                    __nv_bfloat16 hx = __float2bfloat16_rn(vx);
                    __nv_bfloat16 lx = __float2bfloat16_rn(vx - __bfloat162float(hx));
                    __nv_bfloat16 hy = __float2bfloat16_rn(vy);
                    __nv_bfloat16 ly = __float2bfloat16_rn(vy - __bfloat162float(hy));
                    g_Vth[o] = hx;           g_Vtl[o] = lx;
                    g_Vth[o + NSEQ] = hy;    g_Vtl[o + NSEQ] = ly;
                } else if (EPI == 3) {
                    int b = bh >> 3;
                    bool mrow = (mask[b * NSEQ + row] != 0);
                    size_t so = (size_t)bh * NSEQ * NSEQ + (size_t)row * NSEQ + col;
                    size_t apo = (size_t)row * NSEQ + col;
                    bool ok0 = mrow && (mask[b * NSEQ + col] != 0);
                    bool ok1 = mrow && (mask[b * NSEQ + col + 1] != 0);
                    g_S[so]     = ok0 ? (vx + g_AP[apo])     : NEG_INF_F;
                    g_S[so + 1] = ok1 ? (vy + g_AP[apo + 1]) : NEG_INF_F;
                } else if (EPI == 4) {
                    int b = bh >> 3, hh = bh & 7;
                    size_t o = ((size_t)b * NSEQ + row) * DM + hh * DH + col;
                    __nv_bfloat162 h = __floats2bfloat162_rn(vx, vy);
                    float2 f = __bfloat1622float2(h);
                    __nv_bfloat162 l = __floats2bfloat162_rn(vx - f.x, vy - f.y);
                    *(__nv_bfloat162*)&g_Yh[o] = h;
                    *(__nv_bfloat162*)&g_Yl[o] = l;
                } else {
                    Cext[(size_t)row * DM + col]     = vx;
                    Cext[(size_t)row * DM + col + 1] = vy;
                }
            }
        }
    }
}

// ---------------------------------------------------------------------------
// Fused softmax: reads S fp32, writes P as bf16 hi/lo pairs; head-7 rows also
// stream fp32 to d_out's A region.
// ---------------------------------------------------------------------------
__global__ __launch_bounds__(256) void softmax_kernel(float* __restrict__ Aout) {
    __shared__ float red[8];
    __shared__ float bcast;
    const int row = blockIdx.x;
    const float* S = g_S + (size_t)row * NSEQ;
    const int t = threadIdx.x, lane = t & 31, warp = t >> 5;

    float4 v0 = *(const float4*)&S[t * 4];
    float4 v1 = *(const float4*)&S[(t + 256) * 4];

    float m = fmaxf(fmaxf(fmaxf(v0.x, v0.y), fmaxf(v0.z, v0.w)),
                    fmaxf(fmaxf(v1.x, v1.y), fmaxf(v1.z, v1.w)));
#pragma unroll
    for (int o = 16; o; o >>= 1) m = fmaxf(m, __shfl_xor_sync(~0u, m, o));
    if (lane == 0) red[warp] = m;
    __syncthreads();
    if (t == 0) {
        float mm = red[0];
#pragma unroll
        for (int i = 1; i < 8; i++) mm = fmaxf(mm, red[i]);
        bcast = mm;
    }
    __syncthreads();
    m = bcast;

    float4 p0, p1;
    p0.x = expf(v0.x - m); p0.y = expf(v0.y - m);
    p0.z = expf(v0.z - m); p0.w = expf(v0.w - m);
    p1.x = expf(v1.x - m); p1.y = expf(v1.y - m);
    p1.z = expf(v1.z - m); p1.w = expf(v1.w - m);

    float z = p0.x + p0.y + p0.z + p0.w + p1.x + p1.y + p1.z + p1.w;
#pragma unroll
    for (int o = 16; o; o >>= 1) z += __shfl_xor_sync(~0u, z, o);
    if (lane == 0) red[warp] = z;
    __syncthreads();
    if (t == 0) {
        float zz = 0.f;
#pragma unroll
        for (int i = 0; i < 8; i++) zz += red[i];
        bcast = 1.f / zz;
    }
    __syncthreads();
    float zi = bcast;

    p0.x *= zi; p0.y *= zi; p0.z *= zi; p0.w *= zi;
    p1.x *= zi; p1.y *= zi; p1.z *= zi; p1.w *= zi;

    size_t pb = (size_t)row * NSEQ;
    uint2 hi, lo;
    split_pack(p0, hi, lo);
    *(uint2*)&g_Ph[pb + t * 4] = hi;
    *(uint2*)&g_Pl[pb + t * 4] = lo;
    split_pack(p1, hi, lo);
    *(uint2*)&g_Ph[pb + (t + 256) * 4] = hi;
    *(uint2*)&g_Pl[pb + (t + 256) * 4] = lo;

    const int bhh = row >> 11;
    if ((bhh & 7) == 7) {
        const int b = bhh >> 3;
        size_t base = OUT_A_OFF + ((size_t)b * NSEQ + (row & (NSEQ - 1))) * NSEQ;
        *(float4*)&Aout[base + t * 4]         = p0;
        *(float4*)&Aout[base + (t + 256) * 4] = p1;
    }
}

// ---------------------------------------------------------------------------
extern "C" void kernel_launch(void* const* d_in, const int* in_sizes, int n_in,
                              void* d_out, int out_size) {
    const float* x    = (const float*)d_in[0];
    const int*   mask = (const int*)  d_in[1];
    const float* Wq   = (const float*)d_in[2];
    const float* Wk   = (const float*)d_in[3];
    const float* Wv   = (const float*)d_in[4];
    const float* Wout = (const float*)d_in[5];
    float* out = (float*)d_out;

    cudaFuncSetAttribute(tgemm<0>, cudaFuncAttributeMaxDynamicSharedMemorySize, SMEM_BYTES);
    cudaFuncSetAttribute(tgemm<1>, cudaFuncAttributeMaxDynamicSharedMemorySize, SMEM_BYTES);
    cudaFuncSetAttribute(tgemm<2>, cudaFuncAttributeMaxDynamicSharedMemorySize, SMEM_BYTES);
    cudaFuncSetAttribute(tgemm<3>, cudaFuncAttributeMaxDynamicSharedMemorySize, SMEM_BYTES);
    cudaFuncSetAttribute(tgemm<4>, cudaFuncAttributeMaxDynamicSharedMemorySize, SMEM_BYTES);
    cudaFuncSetAttribute(tgemm<5>, cudaFuncAttributeMaxDynamicSharedMemorySize, SMEM_BYTES);

    // operand pre-split (tiny, bandwidth-bound)
    __nv_bfloat16 *xh, *xl, *wqh, *wql, *wkh, *wkl, *wvh, *wvl, *woh, *wol;
    cudaGetSymbolAddress((void**)&xh,  g_xh);  cudaGetSymbolAddress((void**)&xl,  g_xl);
    cudaGetSymbolAddress((void**)&wqh, g_Wqh); cudaGetSymbolAddress((void**)&wql, g_Wql);
    cudaGetSymbolAddress((void**)&wkh, g_Wkh); cudaGetSymbolAddress((void**)&wkl, g_Wkl);
    cudaGetSymbolAddress((void**)&wvh, g_Wvh); cudaGetSymbolAddress((void**)&wvl, g_Wvl);
    cudaGetSymbolAddress((void**)&woh, g_Woh); cudaGetSymbolAddress((void**)&wol, g_Wol);

    conv_kernel<<<(BSZ * NSEQ * DM) / 1024, 256>>>(x, xh, xl);
    conv_kernel<<<(DM * DM) / 1024, 256>>>(Wq, wqh, wql);
    conv_kernel<<<(DM * DM) / 1024, 256>>>(Wk, wkh, wkl);
    conv_kernel<<<(DM * DM) / 1024, 256>>>(Wv, wvh, wvl);
    conv_kernel<<<(DM * DM) / 1024, 256>>>(Wout, woh, wol);

    w_kernel<<<4, 256>>>();
    ap_kernel<<<((size_t)NSEQ * NSEQ / 2) / 256, 256>>>();

    dim3 gproj(DM / 128, (BSZ * NSEQ) / 128);          // (8, 64)
    tgemm<0><<<gproj, 256, SMEM_BYTES>>>(nullptr, nullptr);
    tgemm<1><<<gproj, 256, SMEM_BYTES>>>(nullptr, nullptr);
    tgemm<2><<<gproj, 256, SMEM_BYTES>>>(nullptr, nullptr);

    tgemm<3><<<dim3(NSEQ / 128, NSEQ / 128, BSZ * NH), 256, SMEM_BYTES>>>(nullptr, mask);

    softmax_kernel<<<BSZ * NH * NSEQ, 256>>>(out);

    tgemm<4><<<dim3(1, NSEQ / 128, BSZ * NH), 256, SMEM_BYTES>>>(nullptr, nullptr);

    tgemm<5><<<gproj, 256, SMEM_BYTES>>>(out, nullptr);
}